// round 16
// baseline (speedup 1.0000x reference)
#include <cuda_runtime.h>

// Batched 12x12 complex-DFT magnitude, approx pass only.
// R12 (4th resubmit after repeated infra timeouts) = R6 skeleton (single
// phase, one barrier, 32 pairs x 7 rows = 224 thr, 3 blocks/SM) + folded-x
// stage A:
//   staging stores x0, x6 raw and xs_j=x_j+x_{12-j} (rows 1..5),
//   xd_j=x_j-x_{12-j} (rows 7..11); stage A then needs only 7 weight terms
//   per output row (even wre on xs, odd wim on xd), via a 49-entry per-row
//   folded weight table sWF (broadcast LDS).
// Stage B: 7-term symmetric dot products (register LUT, compile-time idx).
// Hermitian output mirror rows 7..11. f32x2 packing (2 tiles/lane).

typedef unsigned long long u64;

__device__ __forceinline__ u64 pk2(float lo, float hi) {
    u64 r; asm("mov.b64 %0,{%1,%2};" : "=l"(r) : "f"(lo), "f"(hi)); return r;
}
__device__ __forceinline__ void upk2(u64 v, float& lo, float& hi) {
    asm("mov.b64 {%0,%1},%2;" : "=f"(lo), "=f"(hi) : "l"(v));
}
__device__ __forceinline__ u64 fma2(u64 a, u64 b, u64 c) {
    u64 d; asm("fma.rn.f32x2 %0,%1,%2,%3;" : "=l"(d) : "l"(a), "l"(b), "l"(c)); return d;
}
__device__ __forceinline__ u64 add2(u64 a, u64 b) {
    u64 d; asm("add.rn.f32x2 %0,%1,%2;" : "=l"(d) : "l"(a), "l"(b)); return d;
}
__device__ __forceinline__ u64 mul2(u64 a, u64 b) {
    u64 d; asm("mul.rn.f32x2 %0,%1,%2;" : "=l"(d) : "l"(a), "l"(b)); return d;
}
__device__ __forceinline__ float sqrt_ap(float x) {
    float r; asm("sqrt.approx.f32 %0,%1;" : "=f"(r) : "f"(x)); return r;
}
#define NEG1 0xBF800000BF800000ULL
__device__ __forceinline__ u64 sub2(u64 a, u64 b) { return fma2(b, NEG1, a); }

#define PITCH 146    // u64 pitch per pair (even -> 16B-aligned rows)
#define NPAIR 32
#define NROW  7
#define NTHR  224

__global__ void __launch_bounds__(NTHR, 3)
dft_mag_kernel(const float* __restrict__ x,
               const float* __restrict__ wr,
               const float* __restrict__ wi,
               float* __restrict__ out, int size)
{
    // rows per pair: 0=x0, 1..5=xs_j, 6=x6, 7..11=xd_j (j=row-6)
    __shared__ u64 sX[NPAIR][PITCH];
    // folded stage-A weights: sWF[r*7+j'] = {dup wre_rep, dup wim_signed}
    __shared__ ulonglong2 sWF[49];
    __shared__ ulonglong2 sLUT[8];     // stage-B reps m=0..6

    const int t = threadIdx.x;

    // ---- weight prep ----
    if (t < 7) {
        float qa = rintf(wr[12 + t] * 65535.0f) * (1.0f / 65536.0f);
        float qb = rintf(wi[12 + t] * 65535.0f) * (1.0f / 65536.0f);
        ulonglong2 w; w.x = pk2(qa, qa); w.y = pk2(qb, qb);
        sLUT[t] = w;
    }
    if (t < 49) {
        int rr = t / 7, jj = t % 7;
        int m = (rr * jj) % 12;
        int me = (m <= 6) ? m : 12 - m;
        float qa = rintf(wr[12 + me] * 65535.0f) * (1.0f / 65536.0f);
        float qb;
        if (m <= 6)  qb =  rintf(wi[12 + m] * 65535.0f)        * (1.0f / 65536.0f);
        else         qb = -rintf(wi[12 + (12 - m)] * 65535.0f) * (1.0f / 65536.0f);
        ulonglong2 w; w.x = pk2(qa, qa); w.y = pk2(qb, qb);
        sWF[t] = w;
    }

    // ---- staging with fold: 576 items = (pair 0..31, jj 0..5, q 0..2) ----
    const long tilebase = (long)blockIdx.x * (NPAIR * 2);
    const float4* in4 = reinterpret_cast<const float4*>(x);
#pragma unroll
    for (int sw = 0; sw < 3; sw++) {
        int m = sw * NTHR + t;
        if (m < NPAIR * 18) {
            int pair = m / 18;
            int rem = m % 18;
            int jj = rem / 3, q = rem % 3;
            long tg0 = tilebase + 2 * pair;
            if (tg0 + 1 < (long)size) {
                long f0 = tg0 * 36;          // float4 base of tile0
                long f1 = f0 + 36;           // tile1
                if (jj == 0) {
                    // self-paired rows 0 and 6: raw packed
                    float4 a0 = in4[f0 + 0 + q],  b0 = in4[f1 + 0 + q];
                    float4 a6 = in4[f0 + 18 + q], b6 = in4[f1 + 18 + q];
                    u64* d0 = &sX[pair][0 * 12 + 4 * q];
                    d0[0] = pk2(a0.x, b0.x); d0[1] = pk2(a0.y, b0.y);
                    d0[2] = pk2(a0.z, b0.z); d0[3] = pk2(a0.w, b0.w);
                    u64* d6 = &sX[pair][6 * 12 + 4 * q];
                    d6[0] = pk2(a6.x, b6.x); d6[1] = pk2(a6.y, b6.y);
                    d6[2] = pk2(a6.z, b6.z); d6[3] = pk2(a6.w, b6.w);
                } else {
                    int j = jj, j2 = 12 - jj;
                    float4 aj = in4[f0 + j * 3 + q],  bj = in4[f1 + j * 3 + q];
                    float4 am = in4[f0 + j2 * 3 + q], bm = in4[f1 + j2 * 3 + q];
                    u64 pj0 = pk2(aj.x, bj.x), pj1 = pk2(aj.y, bj.y);
                    u64 pj2 = pk2(aj.z, bj.z), pj3 = pk2(aj.w, bj.w);
                    u64 pm0 = pk2(am.x, bm.x), pm1 = pk2(am.y, bm.y);
                    u64 pm2 = pk2(am.z, bm.z), pm3 = pk2(am.w, bm.w);
                    u64* ds = &sX[pair][j * 12 + 4 * q];
                    u64* dd = &sX[pair][(6 + j) * 12 + 4 * q];
                    ds[0] = add2(pj0, pm0); ds[1] = add2(pj1, pm1);
                    ds[2] = add2(pj2, pm2); ds[3] = add2(pj3, pm3);
                    dd[0] = sub2(pj0, pm0); dd[1] = sub2(pj1, pm1);
                    dd[2] = sub2(pj2, pm2); dd[3] = sub2(pj3, pm3);
                }
            }
        }
    }
    __syncthreads();

    const int pr = t / NROW;           // pair (warp spans ~5 values)
    const int r  = t % NROW;           // output row 0..6
    const u64* xp = sX[pr];

    // ---- stage A: 7-term folded rows ----
    u64 rt[12], it[12];
    {   // j'=0: x0, weights m=0
        ulonglong2 w = sWF[r * 7];
        const ulonglong2* xr = reinterpret_cast<const ulonglong2*>(xp);
        ulonglong2 x0 = xr[0], x1 = xr[1], x2 = xr[2],
                   x3 = xr[3], x4 = xr[4], x5 = xr[5];
        u64 xv[12] = { x0.x, x0.y, x1.x, x1.y, x2.x, x2.y,
                       x3.x, x3.y, x4.x, x4.y, x5.x, x5.y };
#pragma unroll
        for (int c = 0; c < 12; c++) {
            rt[c] = mul2(w.x, xv[c]);
            it[c] = mul2(w.y, xv[c]);
        }
    }
#pragma unroll
    for (int j = 1; j <= 5; j++) {     // xs row j -> rt ; xd row 6+j -> it
        ulonglong2 w = sWF[r * 7 + j];
        const ulonglong2* xs = reinterpret_cast<const ulonglong2*>(xp + j * 12);
        const ulonglong2* xd = reinterpret_cast<const ulonglong2*>(xp + (6 + j) * 12);
        ulonglong2 s0 = xs[0], s1 = xs[1], s2 = xs[2],
                   s3 = xs[3], s4 = xs[4], s5 = xs[5];
        ulonglong2 d0 = xd[0], d1 = xd[1], d2 = xd[2],
                   d3 = xd[3], d4 = xd[4], d5 = xd[5];
        u64 sv[12] = { s0.x, s0.y, s1.x, s1.y, s2.x, s2.y,
                       s3.x, s3.y, s4.x, s4.y, s5.x, s5.y };
        u64 dv[12] = { d0.x, d0.y, d1.x, d1.y, d2.x, d2.y,
                       d3.x, d3.y, d4.x, d4.y, d5.x, d5.y };
#pragma unroll
        for (int c = 0; c < 12; c++) {
            rt[c] = fma2(w.x, sv[c], rt[c]);
            it[c] = fma2(w.y, dv[c], it[c]);
        }
    }
    {   // j'=6: x6
        ulonglong2 w = sWF[r * 7 + 6];
        const ulonglong2* xr = reinterpret_cast<const ulonglong2*>(xp + 6 * 12);
        ulonglong2 x0 = xr[0], x1 = xr[1], x2 = xr[2],
                   x3 = xr[3], x4 = xr[4], x5 = xr[5];
        u64 xv[12] = { x0.x, x0.y, x1.x, x1.y, x2.x, x2.y,
                       x3.x, x3.y, x4.x, x4.y, x5.x, x5.y };
#pragma unroll
        for (int c = 0; c < 12; c++) {
            rt[c] = fma2(w.x, xv[c], rt[c]);
            it[c] = fma2(w.y, xv[c], it[c]);
        }
    }

    // ---- stage-B register LUT ----
    u64 wre[7], wim[7];
#pragma unroll
    for (int m = 0; m < 7; m++) {
        ulonglong2 w = sLUT[m];
        wre[m] = w.x; wim[m] = w.y;
    }

    // fold k/(12-k) of rt/it: sums (even wre) and diffs (odd wim)
    u64 rs[6], rd[6], is[6], id[6];
#pragma unroll
    for (int k = 1; k <= 5; k++) {
        rs[k] = add2(rt[k], rt[12 - k]);
        rd[k] = sub2(rt[k], rt[12 - k]);
        is[k] = add2(it[k], it[12 - k]);
        id[k] = sub2(it[k], it[12 - k]);
    }
    const u64 a0 = rt[0], a6 = rt[6], b0 = it[0], b6 = it[6];

    // ---- stage B: 7-term symmetric dot products ----
    float lo[12], hi[12];
#pragma unroll
    for (int c = 0; c < 12; c++) {
        const int m6 = ((6 * c) % 12 == 6) ? 6 : 0;          // compile-time
        u64 p1 = fma2(a6, wre[m6], mul2(a0, wre[0]));
        u64 p4 = fma2(b6, wre[m6], mul2(b0, wre[0]));
        u64 p2p = fma2(b6, wim[m6], mul2(b0, wim[0]));
        u64 p2n = 0;
        u64 p3p = fma2(a6, wim[m6], mul2(a0, wim[0]));
        u64 p3n = 0;
#pragma unroll
        for (int k = 1; k <= 5; k++) {
            const int mk = (k * c) % 12;                     // compile-time
            const int me = (mk <= 6) ? mk : 12 - mk;
            p1 = fma2(rs[k], wre[me], p1);
            p4 = fma2(is[k], wre[me], p4);
            if (mk == 0 || mk == 6) {
                p2p = fma2(is[k], wim[mk], p2p);
                p3p = fma2(rs[k], wim[mk], p3p);
            } else if (mk < 6) {
                p2p = fma2(id[k], wim[mk], p2p);
                p3p = fma2(rd[k], wim[mk], p3p);
            } else {
                p2n = fma2(id[k], wim[12 - mk], p2n);
                p3n = fma2(rd[k], wim[12 - mk], p3n);
            }
        }
        u64 ro = add2(sub2(p1, p2p), p2n);
        u64 io = add2(sub2(p3p, p3n), p4);
        u64 mg = fma2(ro, ro, mul2(io, io));
        float mlo, mhi; upk2(mg, mlo, mhi);
        lo[c] = sqrt_ap(mlo);
        hi[c] = sqrt_ap(mhi);
    }

    // ---- stores: row r + Hermitian mirror row 12-r (r = 1..5) ----
    long item0 = tilebase + 2 * pr;
    float* tb0 = out + item0 * 144;
    float* tb1 = tb0 + 144;
    const bool full = (item0 + 1 < (long)size);
    const int  r2 = 12 - r;

    if (full) {
        float4* o0 = reinterpret_cast<float4*>(tb0 + r * 12);
        float4* o1 = reinterpret_cast<float4*>(tb1 + r * 12);
        o0[0] = make_float4(lo[0], lo[1], lo[2],  lo[3]);
        o0[1] = make_float4(lo[4], lo[5], lo[6],  lo[7]);
        o0[2] = make_float4(lo[8], lo[9], lo[10], lo[11]);
        o1[0] = make_float4(hi[0], hi[1], hi[2],  hi[3]);
        o1[1] = make_float4(hi[4], hi[5], hi[6],  hi[7]);
        o1[2] = make_float4(hi[8], hi[9], hi[10], hi[11]);
        if (r >= 1 && r <= 5) {
            float4* m0 = reinterpret_cast<float4*>(tb0 + r2 * 12);
            float4* m1 = reinterpret_cast<float4*>(tb1 + r2 * 12);
            m0[0] = make_float4(lo[0], lo[11], lo[10], lo[9]);
            m0[1] = make_float4(lo[8], lo[7],  lo[6],  lo[5]);
            m0[2] = make_float4(lo[4], lo[3],  lo[2],  lo[1]);
            m1[0] = make_float4(hi[0], hi[11], hi[10], hi[9]);
            m1[1] = make_float4(hi[8], hi[7],  hi[6],  hi[5]);
            m1[2] = make_float4(hi[4], hi[3],  hi[2],  hi[1]);
        }
    } else if (item0 < (long)size) {       // odd tail (unused at size=100000)
        float* o0 = tb0 + r * 12;
#pragma unroll
        for (int c = 0; c < 12; c++) o0[c] = lo[c];
        if (r >= 1 && r <= 5) {
            float* m0 = tb0 + r2 * 12;
            m0[0] = lo[0];
#pragma unroll
            for (int c = 1; c < 12; c++) m0[c] = lo[12 - c];
        }
    }
}

extern "C" void kernel_launch(void* const* d_in, const int* in_sizes, int n_in,
                              void* d_out, int out_size)
{
    const float* x  = (const float*)d_in[0];
    const float* wr = (const float*)d_in[1];
    const float* wi = (const float*)d_in[2];
    float* out = (float*)d_out;

    int size = in_sizes[0] / 144;                        // 100000
    int blocks = (size + NPAIR * 2 - 1) / (NPAIR * 2);   // 1563
    dft_mag_kernel<<<blocks, NTHR>>>(x, wr, wi, out, size);
}